// round 1
// baseline (speedup 1.0000x reference)
#include <cuda_runtime.h>

#define NPB 15   // prob bins
#define NC  8    // classes
#define NNB 9    // neighbor bins (3x3)
#define HH  512
#define WW  512
#define TX  32
#define TY  16
#define NTHREADS (TX*TY)

__global__ __launch_bounds__(NTHREADS) void nectar_kernel(
    const float* __restrict__ logits,
    const float* __restrict__ vf,
    float* __restrict__ out)
{
    // channel-major smem: lane-consecutive spatial index -> conflict-free
    __shared__ float s_probs[NC][TY + 2][TX + 2];
    __shared__ float s_col[NC][TY][TX + 2];
    __shared__ float s_vf[NC * NNB * NPB];

    const int t  = threadIdx.y * TX + threadIdx.x;
    const int b  = blockIdx.z;
    const int bx = blockIdx.x * TX;
    const int by = blockIdx.y * TY;

    // stage calibration table
    for (int i = t; i < NC * NNB * NPB; i += NTHREADS) s_vf[i] = vf[i];

    const long plane = (long)HH * WW;
    const float* lbase = logits + (long)b * NC * plane;

    // Stage 1: halo softmax -> smem probs (0 outside image, matching SAME/zero pad)
    for (int i = t; i < (TY + 2) * (TX + 2); i += NTHREADS) {
        const int hy = i / (TX + 2);
        const int hx = i % (TX + 2);
        const int gy = by + hy - 1;
        const int gx = bx + hx - 1;
        if (gy >= 0 && gy < HH && gx >= 0 && gx < WW) {
            float v[NC];
            float m = -3.4e38f;
            const float* p0 = lbase + (long)gy * WW + gx;
#pragma unroll
            for (int c = 0; c < NC; c++) {
                v[c] = p0[c * plane];
                m = fmaxf(m, v[c]);
            }
            float s = 0.f;
#pragma unroll
            for (int c = 0; c < NC; c++) {
                v[c] = expf(v[c] - m);
                s += v[c];
            }
#pragma unroll
            for (int c = 0; c < NC; c++)
                s_probs[c][hy][hx] = __fdiv_rn(v[c], s);
        } else {
#pragma unroll
            for (int c = 0; c < NC; c++)
                s_probs[c][hy][hx] = 0.f;
        }
    }
    __syncthreads();

    // Stage 2: vertical 3-sum (separable box filter, pass 1)
    for (int i = t; i < TY * (TX + 2); i += NTHREADS) {
        const int cy = i / (TX + 2);
        const int cx = i % (TX + 2);
#pragma unroll
        for (int c = 0; c < NC; c++)
            s_col[c][cy][cx] = s_probs[c][cy][cx]
                             + s_probs[c][cy + 1][cx]
                             + s_probs[c][cy + 2][cx];
    }
    __syncthreads();

    // Stage 3: horizontal 3-sum, binning, gather, normalize, store
    const int tx = threadIdx.x;
    const int ty = threadIdx.y;
    const int gx = bx + tx;
    const int gy = by + ty;

    float f[NC];
    float s = 0.f;
#pragma unroll
    for (int c = 0; c < NC; c++) {
        const float p    = s_probs[c][ty + 1][tx + 1];
        const float nsum = s_col[c][ty][tx]
                         + s_col[c][ty][tx + 1]
                         + s_col[c][ty][tx + 2];
        // replicate reference rounding exactly: mean = sum/9 ; bin = floor(mean*9)
        const float mean = __fdiv_rn(nsum, 9.0f);
        int lbn = (int)floorf(mean * (float)NNB);
        lbn = max(0, min(lbn, NNB - 1));
        int pbn = (int)floorf(p * (float)NPB);
        pbn = max(0, min(pbn, NPB - 1));
        f[c] = s_vf[(c * NNB + lbn) * NPB + pbn];
        s += f[c];
    }
    if (s == 0.f) s = 1.f;

    float* obase = out + (long)b * NC * plane + (long)gy * WW + gx;
#pragma unroll
    for (int c = 0; c < NC; c++)
        obase[c * plane] = __fdiv_rn(f[c], s);
}

extern "C" void kernel_launch(void* const* d_in, const int* in_sizes, int n_in,
                              void* d_out, int out_size)
{
    const float* logits = (const float*)d_in[0];
    const float* vf     = (const float*)d_in[1];
    float* out          = (float*)d_out;

    dim3 block(TX, TY);
    dim3 grid(WW / TX, HH / TY, 16 /*B*/);
    nectar_kernel<<<grid, block>>>(logits, vf, out);
}

// round 2
// speedup vs baseline: 1.1673x; 1.1673x over previous
#include <cuda_runtime.h>

#define NPB 15   // prob bins
#define NC  8    // classes
#define NNB 9    // neighbor bins (3x3)
#define HH  512
#define WW  512
#define TX  32
#define TY  16
#define NTHREADS (TX*TY)

__global__ __launch_bounds__(NTHREADS, 4) void nectar_kernel(
    const float* __restrict__ logits,
    const float* __restrict__ vf,
    float* __restrict__ out)
{
    // channel-major smem: lane-consecutive spatial index -> conflict-free
    __shared__ float s_probs[NC][TY + 2][TX + 2];
    __shared__ float s_col[NC][TY][TX + 2];
    __shared__ float s_vf[NC * NNB * NPB];

    const int t  = threadIdx.y * TX + threadIdx.x;
    const int b  = blockIdx.z;
    const int bx = blockIdx.x * TX;
    const int by = blockIdx.y * TY;

    // stage calibration table
    for (int i = t; i < NC * NNB * NPB; i += NTHREADS) s_vf[i] = vf[i];

    const long plane = (long)HH * WW;
    const float* lbase = logits + (long)b * NC * plane;

    // Stage 1: halo softmax -> smem probs (0 outside image, matching SAME/zero pad)
    for (int i = t; i < (TY + 2) * (TX + 2); i += NTHREADS) {
        const int hy = i / (TX + 2);
        const int hx = i % (TX + 2);
        const int gy = by + hy - 1;
        const int gx = bx + hx - 1;
        if (gy >= 0 && gy < HH && gx >= 0 && gx < WW) {
            float v[NC];
            float m = -3.4e38f;
            const float* p0 = lbase + (long)gy * WW + gx;
#pragma unroll
            for (int c = 0; c < NC; c++) {
                v[c] = p0[c * plane];
                m = fmaxf(m, v[c]);
            }
            float s = 0.f;
#pragma unroll
            for (int c = 0; c < NC; c++) {
                v[c] = __expf(v[c] - m);
                s += v[c];
            }
            const float inv = __frcp_rn(s);
#pragma unroll
            for (int c = 0; c < NC; c++)
                s_probs[c][hy][hx] = v[c] * inv;
        } else {
#pragma unroll
            for (int c = 0; c < NC; c++)
                s_probs[c][hy][hx] = 0.f;
        }
    }
    __syncthreads();

    // Stage 2: vertical 3-sum (separable box filter, pass 1)
    for (int i = t; i < TY * (TX + 2); i += NTHREADS) {
        const int cy = i / (TX + 2);
        const int cx = i % (TX + 2);
#pragma unroll
        for (int c = 0; c < NC; c++)
            s_col[c][cy][cx] = s_probs[c][cy][cx]
                             + s_probs[c][cy + 1][cx]
                             + s_probs[c][cy + 2][cx];
    }
    __syncthreads();

    // Stage 3: horizontal 3-sum, binning, gather, normalize, store
    const int tx = threadIdx.x;
    const int ty = threadIdx.y;
    const int gx = bx + tx;
    const int gy = by + ty;

    float f[NC];
    float s = 0.f;
#pragma unroll
    for (int c = 0; c < NC; c++) {
        const float p    = s_probs[c][ty + 1][tx + 1];
        const float nsum = s_col[c][ty][tx]
                         + s_col[c][ty][tx + 1]
                         + s_col[c][ty][tx + 2];
        // binned path: keep reference rounding (mean = sum/9 ; bin = floor(mean*9))
        const float mean = __fdiv_rn(nsum, 9.0f);
        int lbn = (int)floorf(mean * (float)NNB);
        lbn = max(0, min(lbn, NNB - 1));
        int pbn = (int)floorf(p * (float)NPB);
        pbn = max(0, min(pbn, NPB - 1));
        f[c] = s_vf[(c * NNB + lbn) * NPB + pbn];
        s += f[c];
    }
    if (s == 0.f) s = 1.f;
    // continuous path: reciprocal-multiply is ~1 ulp vs divide, no binning downstream
    const float invs = __frcp_rn(s);

    float* obase = out + (long)b * NC * plane + (long)gy * WW + gx;
#pragma unroll
    for (int c = 0; c < NC; c++)
        obase[c * plane] = f[c] * invs;
}

extern "C" void kernel_launch(void* const* d_in, const int* in_sizes, int n_in,
                              void* d_out, int out_size)
{
    const float* logits = (const float*)d_in[0];
    const float* vf     = (const float*)d_in[1];
    float* out          = (float*)d_out;

    dim3 block(TX, TY);
    dim3 grid(WW / TX, HH / TY, 16 /*B*/);
    nectar_kernel<<<grid, block>>>(logits, vf, out);
}